// round 7
// baseline (speedup 1.0000x reference)
#include <cuda_runtime.h>
#include <cuda_bf16.h>
#include <stdint.h>
#include <math.h>

// ---------------- problem constants ----------------
#define V_  32000
#define D_  512
#define L_  6
#define FF_ 2048
#define T_  2048
#define B_  2
#define S_  8
#define DS_ 32
#define K_  15

#define BT_ (B_ * T_)          // 4096 tokens
#define NC_ 32                 // scan chunks
#define TC_ (T_ / NC_)         // 64 steps per chunk

// ---------------- device scratch (no allocations allowed) ----------------
__device__ float d_X  [BT_ * D_];
__device__ float d_HN [BT_ * D_];
__device__ float d_GV [BT_ * 2 * D_];
__device__ float d_G  [BT_ * S_];
__device__ float d_RQ [BT_ * S_];
__device__ float d_V  [BT_ * DS_];
__device__ float d_MS [BT_ * S_ * DS_];
__device__ float d_UPc[BT_ * 2 * FF_];
__device__ float d_MEM[B_ * S_ * DS_];
__device__ float d_CHA[B_ * S_ * NC_];
__device__ float d_CHB[B_ * S_ * DS_ * NC_];
__device__ float d_CST[B_ * S_ * DS_ * NC_];

// split-bf16 packed operands, layout per row: [k32 chunk][16 hi words | 16 lo words]
__device__ unsigned d_HN2[BT_ * D_];
__device__ unsigned d_CG2[BT_ * D_];
__device__ unsigned d_RF2[BT_ * S_ * DS_];
__device__ unsigned d_UP2[BT_ * FF_];
__device__ unsigned d_WMU[L_ * 2 * D_ * D_];
__device__ unsigned d_WMD[L_ * D_ * D_];
__device__ unsigned d_WRO[L_ * D_ * S_ * DS_];
__device__ unsigned d_WFF[L_ * 2 * FF_ * D_];
__device__ unsigned d_WOF[L_ * D_ * FF_];
__device__ unsigned d_WEM[V_ * D_];

// ---------------- bf16 split helpers ----------------
__device__ __forceinline__ unsigned pack_hilo(float x0, float x1, unsigned& lo)
{
    __nv_bfloat16 h0 = __float2bfloat16_rn(x0);
    __nv_bfloat16 h1 = __float2bfloat16_rn(x1);
    float l0f = x0 - __bfloat162float(h0);
    float l1f = x1 - __bfloat162float(h1);
    __nv_bfloat16 l0 = __float2bfloat16_rn(l0f);
    __nv_bfloat16 l1 = __float2bfloat16_rn(l1f);
    lo = (unsigned)__bfloat16_as_ushort(l0) | ((unsigned)__bfloat16_as_ushort(l1) << 16);
    return (unsigned)__bfloat16_as_ushort(h0) | ((unsigned)__bfloat16_as_ushort(h1) << 16);
}

__device__ __forceinline__ void mma_bf16(float* c, const unsigned* a, unsigned b0, unsigned b1)
{
    asm volatile(
        "mma.sync.aligned.m16n8k16.row.col.f32.bf16.bf16.f32 "
        "{%0,%1,%2,%3}, {%4,%5,%6,%7}, {%8,%9}, {%0,%1,%2,%3};"
        : "+f"(c[0]), "+f"(c[1]), "+f"(c[2]), "+f"(c[3])
        : "r"(a[0]), "r"(a[1]), "r"(a[2]), "r"(a[3]), "r"(b0), "r"(b1));
}

__device__ __forceinline__ void ldsm4(unsigned& r0, unsigned& r1, unsigned& r2, unsigned& r3,
                                      unsigned saddr)
{
    asm volatile("ldmatrix.sync.aligned.m8n8.x4.shared.b16 {%0,%1,%2,%3}, [%4];"
                 : "=r"(r0), "=r"(r1), "=r"(r2), "=r"(r3) : "r"(saddr));
}

__device__ __forceinline__ void cp16(unsigned saddr, const void* g)
{
    asm volatile("cp.async.cg.shared.global [%0], [%1], 16;" :: "r"(saddr), "l"(g));
}

// ---------------- split-bf16 tensor GEMM: C[M,N] = A @ W^T (+R) ----------------
// 128x128 block tile, 16 warps (4x4), 32x32 warp tile, k-chunk 32,
// 4-stage cp.async pipeline, ldmatrix, 3-term split-bf16.
#define TW_ 20                   // padded row stride (words); conflict-free & 16B-aligned
#define TILE_W_ (128 * TW_)      // 2560 words per tile
#define STAGE_W_ (4 * TILE_W_)   // Ahi,Alo,Bhi,Blo
#define NSTG_ 4
#define SMEM_B_ (NSTG_ * STAGE_W_ * 4)   // 163840 bytes

template<bool RES>
__global__ __launch_bounds__(512, 1)
void bsgemm_kernel(const unsigned* __restrict__ A, const unsigned* __restrict__ W,
                   const float* __restrict__ R, float* __restrict__ C,
                   int M, int N, int KC)   // KC = K/32, KC >= 3
{
    extern __shared__ unsigned sm[];
    const unsigned sbase = (unsigned)__cvta_generic_to_shared(sm);
    const int tid = threadIdx.x, wid = tid >> 5, lane = tid & 31;
    const int grp = lane >> 2, kin = lane & 3;
    const int wm = (wid & 3) * 32, wn = (wid >> 2) * 32;
    const int row0 = blockIdx.y * 128, col0 = blockIdx.x * 128;

    // one cp.async slot per thread: (row cr, quarter cj)
    const int cr = tid >> 2, cj = tid & 3;
    const unsigned so = (unsigned)(cr * TW_ + cj * 4) * 4u;
    const unsigned* Ag = A + ((size_t)(row0 + cr) * KC) * 32 + cj * 4;
    const unsigned* Wg = W + ((size_t)(col0 + cr) * KC) * 32 + cj * 4;

    float acc[2][4][4];
#pragma unroll
    for (int i = 0; i < 2; i++)
#pragma unroll
        for (int j = 0; j < 4; j++)
#pragma unroll
            for (int r = 0; r < 4; r++) acc[i][j][r] = 0.f;

#define LOAD_STAGE(c) do {                                                  \
        const unsigned sb = sbase + (unsigned)(((c) & 3) * STAGE_W_) * 4u;  \
        const unsigned* ap = Ag + (size_t)(c) * 32;                         \
        const unsigned* wp = Wg + (size_t)(c) * 32;                         \
        cp16(sb + so,                     ap);                              \
        cp16(sb + TILE_W_ * 4u + so,      ap + 16);                         \
        cp16(sb + 2u * TILE_W_ * 4u + so, wp);                              \
        cp16(sb + 3u * TILE_W_ * 4u + so, wp + 16);                         \
        asm volatile("cp.async.commit_group;" ::: "memory");                \
    } while (0)

    LOAD_STAGE(0);
    LOAD_STAGE(1);
    LOAD_STAGE(2);

    const int lrow_add = (lane & 7) + ((lane >> 3) & 1) * 8;
    const int lword_add = (lane >> 4) * 4;

    for (int c = 0; c < KC; c++) {
        // wait until chunk c's group is complete (tail ladder)
        if (c + 3 <= KC)
            asm volatile("cp.async.wait_group 2;" ::: "memory");
        else if (c + 2 == KC)
            asm volatile("cp.async.wait_group 1;" ::: "memory");
        else
            asm volatile("cp.async.wait_group 0;" ::: "memory");
        __syncthreads();

        if (c + 3 < KC) LOAD_STAGE(c + 3);

        const unsigned sb = sbase + (unsigned)((c & 3) * STAGE_W_) * 4u;
        const unsigned aHi = sb;
        const unsigned aLo = sb + TILE_W_ * 4u;
        const unsigned bHi = sb + 2u * TILE_W_ * 4u;
        const unsigned bLo = sb + 3u * TILE_W_ * 4u;

#pragma unroll
        for (int s16 = 0; s16 < 2; s16++) {
            const int kw = s16 * 8 + lword_add;
            unsigned ah[2][4], al[2][4], bh[4][2], bl[4][2];
#pragma unroll
            for (int i = 0; i < 2; i++) {
                const unsigned off = (unsigned)((wm + i * 16 + lrow_add) * TW_ + kw) * 4u;
                ldsm4(ah[i][0], ah[i][1], ah[i][2], ah[i][3], aHi + off);
                ldsm4(al[i][0], al[i][1], al[i][2], al[i][3], aLo + off);
            }
#pragma unroll
            for (int jj = 0; jj < 2; jj++) {
                const unsigned off = (unsigned)((wn + jj * 16 + lrow_add) * TW_ + kw) * 4u;
                unsigned q0, q1, q2, q3;
                ldsm4(q0, q1, q2, q3, bHi + off);
                bh[jj * 2][0] = q0; bh[jj * 2 + 1][0] = q1;
                bh[jj * 2][1] = q2; bh[jj * 2 + 1][1] = q3;
                ldsm4(q0, q1, q2, q3, bLo + off);
                bl[jj * 2][0] = q0; bl[jj * 2 + 1][0] = q1;
                bl[jj * 2][1] = q2; bl[jj * 2 + 1][1] = q3;
            }
#pragma unroll
            for (int j = 0; j < 4; j++)
#pragma unroll
                for (int i = 0; i < 2; i++) {
                    mma_bf16(acc[i][j], ah[i], bh[j][0], bh[j][1]);
                    mma_bf16(acc[i][j], al[i], bh[j][0], bh[j][1]);
                    mma_bf16(acc[i][j], ah[i], bl[j][0], bl[j][1]);
                }
        }
    }
#undef LOAD_STAGE

    // epilogue
    const int orow0 = row0 + wm + grp;
    const int ocol0 = col0 + wn + 2 * kin;
#pragma unroll
    for (int i = 0; i < 2; i++) {
#pragma unroll
        for (int j = 0; j < 4; j++) {
            const size_t o0 = (size_t)(orow0 + i * 16) * N + ocol0 + j * 8;
            const size_t o1 = (size_t)(orow0 + i * 16 + 8) * N + ocol0 + j * 8;
            float2 v0 = make_float2(acc[i][j][0], acc[i][j][1]);
            float2 v1 = make_float2(acc[i][j][2], acc[i][j][3]);
            if (RES) {
                float2 r0 = *reinterpret_cast<const float2*>(R + o0);
                float2 r1 = *reinterpret_cast<const float2*>(R + o1);
                v0.x += r0.x; v0.y += r0.y;
                v1.x += r1.x; v1.y += r1.y;
            }
            *reinterpret_cast<float2*>(C + o0) = v0;
            *reinterpret_cast<float2*>(C + o1) = v1;
        }
    }
}

// ---------------- weight converter -> packed split layout (k32 chunks) ----------------
__global__ __launch_bounds__(256) void convert_split_kernel(
    const float* __restrict__ src, unsigned* __restrict__ dst,
    int nRows, int K, int group, int dstride, int dbase)
{
    int kp2 = K >> 1;
    int idx = blockIdx.x * 256 + threadIdx.x;
    if (idx >= nRows * kp2) return;
    int n = idx / kp2, p = idx - n * kp2;
    float x = src[(size_t)n * K + 2 * p];
    float y = src[(size_t)n * K + 2 * p + 1];
    unsigned lo, hi = pack_hilo(x, y, lo);
    int dn = (n / group) * dstride + dbase + (n % group);
    size_t base = ((size_t)dn * (K >> 5) + (p >> 4)) * 32 + (p & 15);
    dst[base] = hi;
    dst[base + 16] = lo;
}

// ---------------- embed gather + rmsnorm(ln_in) -> fp32 X ----------------
__global__ __launch_bounds__(256) void embed_norm_kernel(
    const int* __restrict__ tokens, const float* __restrict__ embed,
    const float* __restrict__ w, float* __restrict__ out)
{
    const int bt = blockIdx.x;
    const int tid = threadIdx.x;
    const int tok = tokens[bt];
    const float* row = embed + (size_t)tok * D_;
    float x0 = row[tid], x1 = row[tid + 256];
    __shared__ float red[256];
    red[tid] = x0 * x0 + x1 * x1;
    __syncthreads();
    for (int s = 128; s > 0; s >>= 1) {
        if (tid < s) red[tid] += red[tid + s];
        __syncthreads();
    }
    float scale = rsqrtf(red[0] / (float)D_ + 1e-6f);
    out[bt * D_ + tid]       = x0 * scale * w[tid];
    out[bt * D_ + tid + 256] = x1 * scale * w[tid + 256];
}

// ---------------- rmsnorm -> fp32 (story-memory branch) ----------------
__global__ __launch_bounds__(256) void rmsnorm_kernel(
    const float* __restrict__ X, const float* __restrict__ w, float* __restrict__ O)
{
    const int bt = blockIdx.x;
    const int tid = threadIdx.x;
    float x0 = X[bt * D_ + tid], x1 = X[bt * D_ + tid + 256];
    __shared__ float red[256];
    red[tid] = x0 * x0 + x1 * x1;
    __syncthreads();
    for (int s = 128; s > 0; s >>= 1) {
        if (tid < s) red[tid] += red[tid + s];
        __syncthreads();
    }
    float scale = rsqrtf(red[0] / (float)D_ + 1e-6f);
    O[bt * D_ + tid]       = x0 * scale * w[tid];
    O[bt * D_ + tid + 256] = x1 * scale * w[tid + 256];
}

// ---------------- rmsnorm -> split-packed (K=512) ----------------
__global__ __launch_bounds__(256) void rmsnorm_split_kernel(
    const float* __restrict__ X, const float* __restrict__ w, unsigned* __restrict__ O)
{
    const int bt = blockIdx.x;
    const int t = threadIdx.x;
    float x0 = X[(size_t)bt * D_ + 2 * t];
    float x1 = X[(size_t)bt * D_ + 2 * t + 1];
    __shared__ float red[256];
    red[t] = x0 * x0 + x1 * x1;
    __syncthreads();
    for (int s = 128; s > 0; s >>= 1) {
        if (t < s) red[t] += red[t + s];
        __syncthreads();
    }
    float sc = rsqrtf(red[0] / (float)D_ + 1e-6f);
    float y0 = x0 * sc * w[2 * t], y1 = x1 * sc * w[2 * t + 1];
    unsigned lo, hi = pack_hilo(y0, y1, lo);
    size_t base = ((size_t)bt * 16 + (t >> 4)) * 32 + (t & 15);
    O[base] = hi; O[base + 16] = lo;
}

// ---------------- causal depthwise conv + gate -> split-packed (K=512) ----------------
__global__ __launch_bounds__(256) void conv_gate_split_kernel(
    const float* __restrict__ GV, const float* __restrict__ cw, unsigned* __restrict__ CG2)
{
    const int idx = blockIdx.x * 256 + threadIdx.x;
    const int w = idx & 255;
    const int bt = idx >> 8;
    const int b = bt / T_, t = bt - b * T_;
    const int d0 = 2 * w;
    float s0 = 0.f, s1 = 0.f;
#pragma unroll
    for (int j = 0; j < K_; j++) {
        int tt = t - (K_ - 1) + j;
        if (tt >= 0) {
            const float* row = GV + (size_t)(b * T_ + tt) * (2 * D_) + D_;
            s0 += row[d0]     * cw[d0 * K_ + j];
            s1 += row[d0 + 1] * cw[(d0 + 1) * K_ + j];
        }
    }
    float g0 = GV[(size_t)bt * (2 * D_) + d0];
    float g1 = GV[(size_t)bt * (2 * D_) + d0 + 1];
    float y0 = s0 / (1.f + expf(-g0));
    float y1 = s1 / (1.f + expf(-g1));
    unsigned lo, hi = pack_hilo(y0, y1, lo);
    size_t base = ((size_t)bt * 16 + (w >> 4)) * 32 + (w & 15);
    CG2[base] = hi; CG2[base + 16] = lo;
}

// ---------------- small projections ----------------
__global__ __launch_bounds__(256) void smallproj_kernel(
    const float* __restrict__ HN, const float* __restrict__ wg,
    const float* __restrict__ rqw, const float* __restrict__ wv,
    float* __restrict__ G, float* __restrict__ RQ, float* __restrict__ Vv)
{
    const int bt = blockIdx.x;
    const int tid = threadIdx.x;
    __shared__ float h[D_];
    h[tid] = HN[bt * D_ + tid];
    h[tid + 256] = HN[bt * D_ + tid + 256];
    __syncthreads();
    const int warp = tid >> 5, lane = tid & 31;
    for (int o = warp; o < S_ + S_ + DS_; o += 8) {
        const float* wrow;
        if (o < S_) wrow = wg + o * D_;
        else if (o < 2 * S_) wrow = rqw + (o - S_) * D_;
        else wrow = wv + (o - 2 * S_) * D_;
        float s = 0.f;
#pragma unroll
        for (int k = lane; k < D_; k += 32) s += h[k] * wrow[k];
#pragma unroll
        for (int off = 16; off > 0; off >>= 1) s += __shfl_down_sync(0xffffffffu, s, off);
        if (lane == 0) {
            if (o < S_) G[bt * S_ + o] = 1.f / (1.f + expf(-s));
            else if (o < 2 * S_) RQ[bt * S_ + (o - S_)] = s;
            else Vv[bt * DS_ + (o - 2 * S_)] = s;
        }
    }
}

// ---------------- chunked linear-recurrence scan ----------------
__global__ __launch_bounds__(256) void scan_pass1_kernel(
    const float* __restrict__ G, const float* __restrict__ Vv,
    float* __restrict__ CHA, float* __restrict__ CHB)
{
    const int idx = blockIdx.x * 256 + threadIdx.x;
    const int ds = idx % DS_;
    const int s  = (idx / DS_) % S_;
    const int c  = (idx / (DS_ * S_)) % NC_;
    const int b  = idx / (DS_ * S_ * NC_);
    float A = 1.f, Bv = 0.f;
    const int t0 = c * TC_;
    for (int t = t0; t < t0 + TC_; t++) {
        float g = G[(size_t)(b * T_ + t) * S_ + s];
        float a = 1.f - g;
        float bb = g * Vv[(size_t)(b * T_ + t) * DS_ + ds];
        A = a * A;
        Bv = a * Bv + bb;
    }
    CHB[((size_t)(b * S_ + s) * DS_ + ds) * NC_ + c] = Bv;
    if (ds == 0) CHA[(size_t)(b * S_ + s) * NC_ + c] = A;
}

__global__ __launch_bounds__(512) void scan_pass2_kernel(
    const float* __restrict__ CHA, const float* __restrict__ CHB,
    float* __restrict__ MEM, float* __restrict__ CST)
{
    const int idx = threadIdx.x;
    const int ds = idx % DS_;
    const int s  = (idx / DS_) % S_;
    const int b  = idx / (DS_ * S_);
    float st = MEM[idx];
    for (int c = 0; c < NC_; c++) {
        CST[((size_t)(b * S_ + s) * DS_ + ds) * NC_ + c] = st;
        float A = CHA[(size_t)(b * S_ + s) * NC_ + c];
        float Bv = CHB[((size_t)(b * S_ + s) * DS_ + ds) * NC_ + c];
        st = A * st + Bv;
    }
    MEM[idx] = st;
}

__global__ __launch_bounds__(256) void scan_pass3_kernel(
    const float* __restrict__ G, const float* __restrict__ Vv,
    const float* __restrict__ CST, float* __restrict__ MS)
{
    const int idx = blockIdx.x * 256 + threadIdx.x;
    const int ds = idx % DS_;
    const int s  = (idx / DS_) % S_;
    const int c  = (idx / (DS_ * S_)) % NC_;
    const int b  = idx / (DS_ * S_ * NC_);
    float m = CST[((size_t)(b * S_ + s) * DS_ + ds) * NC_ + c];
    const int t0 = c * TC_;
    for (int t = t0; t < t0 + TC_; t++) {
        float g = G[(size_t)(b * T_ + t) * S_ + s];
        float bb = g * Vv[(size_t)(b * T_ + t) * DS_ + ds];
        m = (1.f - g) * m + bb;
        MS[(size_t)(b * T_ + t) * (S_ * DS_) + s * DS_ + ds] = m;
    }
}

// ---------------- softmax read-weights * mem_stack -> split-packed (K=256) ----------------
__global__ __launch_bounds__(128) void rf_split_kernel(
    const float* __restrict__ RQ, const float* __restrict__ MS, unsigned* __restrict__ RF2)
{
    const int bt = blockIdx.x;
    const int t = threadIdx.x;
    __shared__ float q[S_];
    if (t < S_) q[t] = RQ[bt * S_ + t];
    __syncthreads();
    float mx = q[0];
#pragma unroll
    for (int i = 1; i < S_; i++) mx = fmaxf(mx, q[i]);
    float den = 0.f;
#pragma unroll
    for (int i = 0; i < S_; i++) den += expf(q[i] - mx);
    const int k0 = 2 * t;
    const int s = k0 >> 5;
    float wgt = expf(q[s] - mx) / den;
    float y0 = wgt * MS[(size_t)bt * 256 + k0];
    float y1 = wgt * MS[(size_t)bt * 256 + k0 + 1];
    unsigned lo, hi = pack_hilo(y0, y1, lo);
    size_t base = ((size_t)bt * 8 + (t >> 4)) * 32 + (t & 15);
    RF2[base] = hi; RF2[base + 16] = lo;
}

// ---------------- silu(gate)*up -> split-packed (K=2048) ----------------
__global__ __launch_bounds__(256) void silu_split_kernel(
    const float* __restrict__ UPc, unsigned* __restrict__ UP2)
{
    const int idx = blockIdx.x * 256 + threadIdx.x;
    const int bt = idx >> 10;
    const int w = idx & 1023;
    const int f0 = 2 * w;
    float a0 = UPc[(size_t)bt * 4096 + f0];
    float a1 = UPc[(size_t)bt * 4096 + f0 + 1];
    float b0 = UPc[(size_t)bt * 4096 + 2048 + f0];
    float b1 = UPc[(size_t)bt * 4096 + 2048 + f0 + 1];
    float y0 = a0 / (1.f + expf(-a0)) * b0;
    float y1 = a1 / (1.f + expf(-a1)) * b1;
    unsigned lo, hi = pack_hilo(y0, y1, lo);
    size_t base = ((size_t)bt * 64 + (w >> 4)) * 32 + (w & 15);
    UP2[base] = hi; UP2[base + 16] = lo;
}

// ---------------- zero memory ----------------
__global__ void zero_mem_kernel(float* __restrict__ M)
{
    M[threadIdx.x] = 0.f;
}

// ---------------- host orchestration ----------------
static void* devptr(const void* symbol) {
    void* p = nullptr;
    cudaGetSymbolAddress(&p, symbol);
    return p;
}

static inline int cblocks(long long threads) { return (int)((threads + 255) / 256); }

extern "C" void kernel_launch(void* const* d_in, const int* in_sizes, int n_in,
                              void* d_out, int out_size)
{
    const int*   tokens    = (const int*)  d_in[0];
    const float* embed     = (const float*)d_in[1];
    const float* ln_in     = (const float*)d_in[2];
    const float* ln1       = (const float*)d_in[3];
    const float* mixer_up  = (const float*)d_in[4];
    const float* conv_w    = (const float*)d_in[5];
    const float* mixer_down= (const float*)d_in[6];
    const float* ln_mem    = (const float*)d_in[7];
    const float* wg        = (const float*)d_in[8];
    const float* wv        = (const float*)d_in[9];
    const float* rq        = (const float*)d_in[10];
    const float* ro        = (const float*)d_in[11];
    const float* ln2       = (const float*)d_in[12];
    const float* Wgf       = (const float*)d_in[13];
    const float* Wuf       = (const float*)d_in[14];
    const float* Wof       = (const float*)d_in[15];
    const float* ln_out    = (const float*)d_in[16];
    float* out = (float*)d_out;

    float* X   = (float*)devptr(d_X);
    float* HN  = (float*)devptr(d_HN);
    float* GV  = (float*)devptr(d_GV);
    float* G   = (float*)devptr(d_G);
    float* RQ  = (float*)devptr(d_RQ);
    float* Vv  = (float*)devptr(d_V);
    float* MS  = (float*)devptr(d_MS);
    float* UPc = (float*)devptr(d_UPc);
    float* MEM = (float*)devptr(d_MEM);
    float* CHA = (float*)devptr(d_CHA);
    float* CHB = (float*)devptr(d_CHB);
    float* CST = (float*)devptr(d_CST);

    unsigned* HN2 = (unsigned*)devptr(d_HN2);
    unsigned* CG2 = (unsigned*)devptr(d_CG2);
    unsigned* RF2 = (unsigned*)devptr(d_RF2);
    unsigned* UP2 = (unsigned*)devptr(d_UP2);
    unsigned* WMU = (unsigned*)devptr(d_WMU);
    unsigned* WMD = (unsigned*)devptr(d_WMD);
    unsigned* WRO = (unsigned*)devptr(d_WRO);
    unsigned* WFF = (unsigned*)devptr(d_WFF);
    unsigned* WOF = (unsigned*)devptr(d_WOF);
    unsigned* WEM = (unsigned*)devptr(d_WEM);

    cudaFuncSetAttribute(bsgemm_kernel<false>, cudaFuncAttributeMaxDynamicSharedMemorySize, SMEM_B_);
    cudaFuncSetAttribute(bsgemm_kernel<true>,  cudaFuncAttributeMaxDynamicSharedMemorySize, SMEM_B_);

    // ---- launch order arranged so launch index 5 (ncu -s 5 -c 1) is a bsgemm ----
    {
        int r;
        r = L_ * 2 * D_;   // [0]
        convert_split_kernel<<<cblocks((long long)r * (D_/2)), 256>>>(mixer_up, WMU, r, D_, r, r, 0);
        r = L_ * D_;       // [1]
        convert_split_kernel<<<cblocks((long long)r * (D_/2)), 256>>>(mixer_down, WMD, r, D_, r, r, 0);
    }
    zero_mem_kernel<<<1, B_ * S_ * DS_>>>(MEM);               // [2]
    embed_norm_kernel<<<BT_, 256>>>(tokens, embed, ln_in, X); // [3]

    const int scanThreads = B_ * S_ * DS_ * NC_;   // 16384

    for (int i = 0; i < L_; i++) {
        const float* ln1_i = ln1 + i * D_;
        const float* cw_i  = conv_w + (size_t)i * D_ * K_;
        const float* lnm_i = ln_mem + i * D_;
        const float* wg_i  = wg + (size_t)i * S_ * D_;
        const float* wv_i  = wv + (size_t)i * DS_ * D_;
        const float* rq_i  = rq + (size_t)i * S_ * D_;
        const float* ln2_i = ln2 + i * D_;

        const unsigned* wmu_i = WMU + (size_t)i * 2 * D_ * D_;
        const unsigned* wmd_i = WMD + (size_t)i * D_ * D_;
        const unsigned* wro_i = WRO + (size_t)i * D_ * S_ * DS_;
        const unsigned* wff_i = WFF + (size_t)i * 2 * FF_ * D_;
        const unsigned* wof_i = WOF + (size_t)i * D_ * FF_;

        // mixer branch
        rmsnorm_split_kernel<<<BT_, 256>>>(X, ln1_i, HN2);    // [4] on i==0
        bsgemm_kernel<false><<<dim3(2 * D_ / 128, BT_ / 128), 512, SMEM_B_>>>(
            HN2, wmu_i, nullptr, GV, BT_, 2 * D_, D_ / 32);   // [5] on i==0 -> profiled

        if (i == 0) {
            // remaining weight conversions (before their first use)
            int r;
            r = L_ * D_;
            convert_split_kernel<<<cblocks((long long)r * (S_*DS_/2)), 256>>>(ro, WRO, r, S_*DS_, r, r, 0);
            r = L_ * FF_;
            convert_split_kernel<<<cblocks((long long)r * (D_/2)), 256>>>(Wgf, WFF, r, D_, FF_, 2*FF_, 0);
            r = L_ * FF_;
            convert_split_kernel<<<cblocks((long long)r * (D_/2)), 256>>>(Wuf, WFF, r, D_, FF_, 2*FF_, FF_);
            r = L_ * D_;
            convert_split_kernel<<<cblocks((long long)r * (FF_/2)), 256>>>(Wof, WOF, r, FF_, r, r, 0);
            r = V_;
            convert_split_kernel<<<cblocks((long long)r * (D_/2)), 256>>>(embed, WEM, r, D_, r, r, 0);
        }

        conv_gate_split_kernel<<<BT_, 256>>>(GV, cw_i, CG2);
        bsgemm_kernel<true><<<dim3(D_ / 128, BT_ / 128), 512, SMEM_B_>>>(
            CG2, wmd_i, X, X, BT_, D_, D_ / 32);

        // story memory branch
        rmsnorm_kernel<<<BT_, 256>>>(X, lnm_i, HN);
        smallproj_kernel<<<BT_, 256>>>(HN, wg_i, rq_i, wv_i, G, RQ, Vv);
        scan_pass1_kernel<<<scanThreads / 256, 256>>>(G, Vv, CHA, CHB);
        scan_pass2_kernel<<<1, B_ * S_ * DS_>>>(CHA, CHB, MEM, CST);
        scan_pass3_kernel<<<scanThreads / 256, 256>>>(G, Vv, CST, MS);
        rf_split_kernel<<<BT_, 128>>>(RQ, MS, RF2);
        bsgemm_kernel<true><<<dim3(D_ / 128, BT_ / 128), 512, SMEM_B_>>>(
            RF2, wro_i, X, X, BT_, D_, S_ * DS_ / 32);

        // FFN branch (fused gate+up GEMM, N = 4096)
        rmsnorm_split_kernel<<<BT_, 256>>>(X, ln2_i, HN2);
        bsgemm_kernel<false><<<dim3(2 * FF_ / 128, BT_ / 128), 512, SMEM_B_>>>(
            HN2, wff_i, nullptr, UPc, BT_, 2 * FF_, D_ / 32);
        silu_split_kernel<<<cblocks((long long)BT_ * (FF_ / 2)), 256>>>(UPc, UP2);
        bsgemm_kernel<true><<<dim3(D_ / 128, BT_ / 128), 512, SMEM_B_>>>(
            UP2, wof_i, X, X, BT_, D_, FF_ / 32);
    }

    // tied head
    rmsnorm_split_kernel<<<BT_, 256>>>(X, ln_out, HN2);
    bsgemm_kernel<false><<<dim3(V_ / 128, BT_ / 128), 512, SMEM_B_>>>(
        HN2, WEM, nullptr, out, BT_, V_, D_ / 32);
}

// round 8
// speedup vs baseline: 1.1883x; 1.1883x over previous
#include <cuda_runtime.h>
#include <cuda_bf16.h>
#include <stdint.h>
#include <math.h>

// ---------------- problem constants ----------------
#define V_  32000
#define D_  512
#define L_  6
#define FF_ 2048
#define T_  2048
#define B_  2
#define S_  8
#define DS_ 32
#define K_  15

#define BT_ (B_ * T_)          // 4096 tokens
#define NC_ 32                 // scan chunks
#define TC_ (T_ / NC_)         // 64 steps per chunk

// ---------------- device scratch (no allocations allowed) ----------------
__device__ float d_X  [BT_ * D_];
__device__ float d_HN [BT_ * D_];
__device__ float d_GV [BT_ * 2 * D_];
__device__ float d_G  [BT_ * S_];
__device__ float d_RQ [BT_ * S_];
__device__ float d_V  [BT_ * DS_];
__device__ float d_MS [BT_ * S_ * DS_];
__device__ float d_UPc[BT_ * 2 * FF_];
__device__ float d_MEM[B_ * S_ * DS_];
__device__ float d_CHA[B_ * S_ * NC_];
__device__ float d_CHB[B_ * S_ * DS_ * NC_];
__device__ float d_CST[B_ * S_ * DS_ * NC_];

// split-bf16 packed operands, layout per row: [k32 chunk][16 hi words | 16 lo words]
__device__ unsigned d_HN2[BT_ * D_];
__device__ unsigned d_CG2[BT_ * D_];
__device__ unsigned d_RF2[BT_ * S_ * DS_];
__device__ unsigned d_UP2[BT_ * FF_];
__device__ unsigned d_WMU[L_ * 2 * D_ * D_];
__device__ unsigned d_WMD[L_ * D_ * D_];
__device__ unsigned d_WRO[L_ * D_ * S_ * DS_];
__device__ unsigned d_WFF[L_ * 2 * FF_ * D_];
__device__ unsigned d_WOF[L_ * D_ * FF_];
__device__ unsigned d_WEM[V_ * D_];

// ---------------- bf16 split helpers ----------------
__device__ __forceinline__ unsigned pack_hilo(float x0, float x1, unsigned& lo)
{
    __nv_bfloat16 h0 = __float2bfloat16_rn(x0);
    __nv_bfloat16 h1 = __float2bfloat16_rn(x1);
    float l0f = x0 - __bfloat162float(h0);
    float l1f = x1 - __bfloat162float(h1);
    __nv_bfloat16 l0 = __float2bfloat16_rn(l0f);
    __nv_bfloat16 l1 = __float2bfloat16_rn(l1f);
    lo = (unsigned)__bfloat16_as_ushort(l0) | ((unsigned)__bfloat16_as_ushort(l1) << 16);
    return (unsigned)__bfloat16_as_ushort(h0) | ((unsigned)__bfloat16_as_ushort(h1) << 16);
}

__device__ __forceinline__ void mma_bf16(float* c, const unsigned* a, unsigned b0, unsigned b1)
{
    asm volatile(
        "mma.sync.aligned.m16n8k16.row.col.f32.bf16.bf16.f32 "
        "{%0,%1,%2,%3}, {%4,%5,%6,%7}, {%8,%9}, {%0,%1,%2,%3};"
        : "+f"(c[0]), "+f"(c[1]), "+f"(c[2]), "+f"(c[3])
        : "r"(a[0]), "r"(a[1]), "r"(a[2]), "r"(a[3]), "r"(b0), "r"(b1));
}

__device__ __forceinline__ void ldsm4(unsigned& r0, unsigned& r1, unsigned& r2, unsigned& r3,
                                      unsigned saddr)
{
    asm volatile("ldmatrix.sync.aligned.m8n8.x4.shared.b16 {%0,%1,%2,%3}, [%4];"
                 : "=r"(r0), "=r"(r1), "=r"(r2), "=r"(r3) : "r"(saddr));
}

__device__ __forceinline__ void cp16(unsigned saddr, const void* g)
{
    asm volatile("cp.async.cg.shared.global [%0], [%1], 16;" :: "r"(saddr), "l"(g));
}

// ---------------- split-bf16 tensor GEMM: C[M,N] = A @ W^T (+R) ----------------
// 128x64 block tile, 8 warps (4x2), 32x32 warp tile, k-chunk 32, 3-stage cp.async,
// ldmatrix, 3-term split-bf16 with TWO accumulators (hh / cross) per output.
#define TW_ 20
#define A_W_ (128 * TW_)          // 2560 words per A sub-tile
#define B_W_ (64 * TW_)           // 1280 words per B sub-tile
#define STG_W_ (2 * A_W_ + 2 * B_W_)   // 7680 words per stage
#define NSTG_ 3
#define SMEM_B_ (NSTG_ * STG_W_ * 4)   // 92160 bytes

template<bool RES>
__global__ __launch_bounds__(256, 2)
void bsgemm_kernel(const unsigned* __restrict__ A, const unsigned* __restrict__ W,
                   const float* __restrict__ R, float* __restrict__ C,
                   int M, int N, int KC)   // KC = K/32, KC >= 2
{
    extern __shared__ unsigned sm[];
    const unsigned sbase = (unsigned)__cvta_generic_to_shared(sm);
    const int tid = threadIdx.x, wid = tid >> 5, lane = tid & 31;
    const int grp = lane >> 2, kin = lane & 3;
    const int wm = (wid & 3) * 32, wn = (wid >> 2) * 32;
    const int row0 = blockIdx.y * 128, col0 = blockIdx.x * 64;

    // loader slots: A: thread -> (row = tid/2, chunk pair = (tid&1)*2)
    //               B: thread -> (row = tid/4, chunk = tid&3)
    const int ar = tid >> 1, ac = (tid & 1) * 2;
    const int br = tid >> 2, bq = tid & 3;
    const unsigned* Aga = A + ((size_t)(row0 + ar) * KC) * 32 + ac * 4;
    const unsigned* Wgb = W + ((size_t)(col0 + br) * KC) * 32 + bq * 4;
    const unsigned soA = (unsigned)(ar * TW_ + ac * 4) * 4u;
    const unsigned soB = (unsigned)(br * TW_ + bq * 4) * 4u;

    float hh[2][4][4], cr[2][4][4];
#pragma unroll
    for (int i = 0; i < 2; i++)
#pragma unroll
        for (int j = 0; j < 4; j++)
#pragma unroll
            for (int r = 0; r < 4; r++) { hh[i][j][r] = 0.f; cr[i][j][r] = 0.f; }

#define LOAD_STAGE(c, st) do {                                              \
        const unsigned sb = sbase + (unsigned)((st) * STG_W_) * 4u;         \
        const unsigned* ap = Aga + (size_t)(c) * 32;                        \
        const unsigned* wp = Wgb + (size_t)(c) * 32;                        \
        cp16(sb + soA,                 ap);                                 \
        cp16(sb + soA + 16,            ap + 4);                             \
        cp16(sb + A_W_ * 4u + soA,      ap + 16);                           \
        cp16(sb + A_W_ * 4u + soA + 16, ap + 20);                           \
        cp16(sb + 2u * A_W_ * 4u + soB,              wp);                   \
        cp16(sb + 2u * A_W_ * 4u + B_W_ * 4u + soB,  wp + 16);              \
        asm volatile("cp.async.commit_group;" ::: "memory");                \
    } while (0)

    LOAD_STAGE(0, 0);
    LOAD_STAGE(1, 1);

    const int lrow_add = (lane & 7) + ((lane >> 3) & 1) * 8;
    const int lword_add = (lane >> 4) * 4;

    int st = 0, st2 = 2;
    for (int c = 0; c < KC; c++) {
        if (c + 1 < KC)
            asm volatile("cp.async.wait_group 1;" ::: "memory");
        else
            asm volatile("cp.async.wait_group 0;" ::: "memory");
        __syncthreads();

        if (c + 2 < KC) {
            LOAD_STAGE(c + 2, st2);
        }

        const unsigned sb = sbase + (unsigned)(st * STG_W_) * 4u;
        const unsigned aHi = sb;
        const unsigned aLo = sb + A_W_ * 4u;
        const unsigned bHi = sb + 2u * A_W_ * 4u;
        const unsigned bLo = bHi + B_W_ * 4u;

#pragma unroll
        for (int s16 = 0; s16 < 2; s16++) {
            const int kw = s16 * 8 + lword_add;
            unsigned ah[2][4], al[2][4], bh[4][2], bl[4][2];
#pragma unroll
            for (int i = 0; i < 2; i++) {
                const unsigned off = (unsigned)((wm + i * 16 + lrow_add) * TW_ + kw) * 4u;
                ldsm4(ah[i][0], ah[i][1], ah[i][2], ah[i][3], aHi + off);
                ldsm4(al[i][0], al[i][1], al[i][2], al[i][3], aLo + off);
            }
#pragma unroll
            for (int jj = 0; jj < 2; jj++) {
                const unsigned off = (unsigned)((wn + jj * 16 + lrow_add) * TW_ + kw) * 4u;
                unsigned q0, q1, q2, q3;
                ldsm4(q0, q1, q2, q3, bHi + off);
                bh[jj * 2][0] = q0; bh[jj * 2 + 1][0] = q1;
                bh[jj * 2][1] = q2; bh[jj * 2 + 1][1] = q3;
                ldsm4(q0, q1, q2, q3, bLo + off);
                bl[jj * 2][0] = q0; bl[jj * 2 + 1][0] = q1;
                bl[jj * 2][1] = q2; bl[jj * 2 + 1][1] = q3;
            }
#pragma unroll
            for (int j = 0; j < 4; j++)
#pragma unroll
                for (int i = 0; i < 2; i++) {
                    mma_bf16(hh[i][j], ah[i], bh[j][0], bh[j][1]);
                    mma_bf16(cr[i][j], al[i], bh[j][0], bh[j][1]);
                    mma_bf16(cr[i][j], ah[i], bl[j][0], bl[j][1]);
                }
        }
        // rotate stages
        int t = st; st = (st == 2) ? 0 : st + 1;
        st2 = (st2 == 2) ? 0 : st2 + 1; (void)t;
    }
#undef LOAD_STAGE

    // epilogue: combine hh + cr (+R)
    const int orow0 = row0 + wm + grp;
    const int ocol0 = col0 + wn + 2 * kin;
#pragma unroll
    for (int i = 0; i < 2; i++) {
#pragma unroll
        for (int j = 0; j < 4; j++) {
            const size_t o0 = (size_t)(orow0 + i * 16) * N + ocol0 + j * 8;
            const size_t o1 = (size_t)(orow0 + i * 16 + 8) * N + ocol0 + j * 8;
            float2 v0 = make_float2(hh[i][j][0] + cr[i][j][0], hh[i][j][1] + cr[i][j][1]);
            float2 v1 = make_float2(hh[i][j][2] + cr[i][j][2], hh[i][j][3] + cr[i][j][3]);
            if (RES) {
                float2 r0 = *reinterpret_cast<const float2*>(R + o0);
                float2 r1 = *reinterpret_cast<const float2*>(R + o1);
                v0.x += r0.x; v0.y += r0.y;
                v1.x += r1.x; v1.y += r1.y;
            }
            *reinterpret_cast<float2*>(C + o0) = v0;
            *reinterpret_cast<float2*>(C + o1) = v1;
        }
    }
}

// ---------------- weight converter -> packed split layout (k32 chunks) ----------------
__global__ __launch_bounds__(256) void convert_split_kernel(
    const float* __restrict__ src, unsigned* __restrict__ dst,
    int nRows, int K, int group, int dstride, int dbase)
{
    int kp2 = K >> 1;
    int idx = blockIdx.x * 256 + threadIdx.x;
    if (idx >= nRows * kp2) return;
    int n = idx / kp2, p = idx - n * kp2;
    float x = src[(size_t)n * K + 2 * p];
    float y = src[(size_t)n * K + 2 * p + 1];
    unsigned lo, hi = pack_hilo(x, y, lo);
    int dn = (n / group) * dstride + dbase + (n % group);
    size_t base = ((size_t)dn * (K >> 5) + (p >> 4)) * 32 + (p & 15);
    dst[base] = hi;
    dst[base + 16] = lo;
}

// ---------------- embed gather + rmsnorm(ln_in) -> fp32 X; fused MEM zeroing ----------------
__global__ __launch_bounds__(256) void embed_norm_kernel(
    const int* __restrict__ tokens, const float* __restrict__ embed,
    const float* __restrict__ w, float* __restrict__ out, float* __restrict__ MEM)
{
    const int bt = blockIdx.x;
    const int tid = threadIdx.x;
    if (bt == 0) { MEM[tid] = 0.f; MEM[tid + 256] = 0.f; }
    const int tok = tokens[bt];
    const float* row = embed + (size_t)tok * D_;
    float x0 = row[tid], x1 = row[tid + 256];
    __shared__ float red[256];
    red[tid] = x0 * x0 + x1 * x1;
    __syncthreads();
    for (int s = 128; s > 0; s >>= 1) {
        if (tid < s) red[tid] += red[tid + s];
        __syncthreads();
    }
    float scale = rsqrtf(red[0] / (float)D_ + 1e-6f);
    out[bt * D_ + tid]       = x0 * scale * w[tid];
    out[bt * D_ + tid + 256] = x1 * scale * w[tid + 256];
}

// ---------------- rmsnorm -> fp32 (story-memory branch) ----------------
__global__ __launch_bounds__(256) void rmsnorm_kernel(
    const float* __restrict__ X, const float* __restrict__ w, float* __restrict__ O)
{
    const int bt = blockIdx.x;
    const int tid = threadIdx.x;
    float x0 = X[bt * D_ + tid], x1 = X[bt * D_ + tid + 256];
    __shared__ float red[256];
    red[tid] = x0 * x0 + x1 * x1;
    __syncthreads();
    for (int s = 128; s > 0; s >>= 1) {
        if (tid < s) red[tid] += red[tid + s];
        __syncthreads();
    }
    float scale = rsqrtf(red[0] / (float)D_ + 1e-6f);
    O[bt * D_ + tid]       = x0 * scale * w[tid];
    O[bt * D_ + tid + 256] = x1 * scale * w[tid + 256];
}

// ---------------- rmsnorm -> split-packed (K=512) ----------------
__global__ __launch_bounds__(256) void rmsnorm_split_kernel(
    const float* __restrict__ X, const float* __restrict__ w, unsigned* __restrict__ O)
{
    const int bt = blockIdx.x;
    const int t = threadIdx.x;
    float x0 = X[(size_t)bt * D_ + 2 * t];
    float x1 = X[(size_t)bt * D_ + 2 * t + 1];
    __shared__ float red[256];
    red[t] = x0 * x0 + x1 * x1;
    __syncthreads();
    for (int s = 128; s > 0; s >>= 1) {
        if (t < s) red[t] += red[t + s];
        __syncthreads();
    }
    float sc = rsqrtf(red[0] / (float)D_ + 1e-6f);
    float y0 = x0 * sc * w[2 * t], y1 = x1 * sc * w[2 * t + 1];
    unsigned lo, hi = pack_hilo(y0, y1, lo);
    size_t base = ((size_t)bt * 16 + (t >> 4)) * 32 + (t & 15);
    O[base] = hi; O[base + 16] = lo;
}

// ---------------- causal depthwise conv + gate -> split-packed (K=512) ----------------
__global__ __launch_bounds__(256) void conv_gate_split_kernel(
    const float* __restrict__ GV, const float* __restrict__ cw, unsigned* __restrict__ CG2)
{
    const int idx = blockIdx.x * 256 + threadIdx.x;
    const int w = idx & 255;
    const int bt = idx >> 8;
    const int b = bt / T_, t = bt - b * T_;
    const int d0 = 2 * w;
    float s0 = 0.f, s1 = 0.f;
#pragma unroll
    for (int j = 0; j < K_; j++) {
        int tt = t - (K_ - 1) + j;
        if (tt >= 0) {
            const float* row = GV + (size_t)(b * T_ + tt) * (2 * D_) + D_;
            s0 += row[d0]     * cw[d0 * K_ + j];
            s1 += row[d0 + 1] * cw[(d0 + 1) * K_ + j];
        }
    }
    float g0 = GV[(size_t)bt * (2 * D_) + d0];
    float g1 = GV[(size_t)bt * (2 * D_) + d0 + 1];
    float y0 = s0 / (1.f + expf(-g0));
    float y1 = s1 / (1.f + expf(-g1));
    unsigned lo, hi = pack_hilo(y0, y1, lo);
    size_t base = ((size_t)bt * 16 + (w >> 4)) * 32 + (w & 15);
    CG2[base] = hi; CG2[base + 16] = lo;
}

// ---------------- small projections ----------------
__global__ __launch_bounds__(256) void smallproj_kernel(
    const float* __restrict__ HN, const float* __restrict__ wg,
    const float* __restrict__ rqw, const float* __restrict__ wv,
    float* __restrict__ G, float* __restrict__ RQ, float* __restrict__ Vv)
{
    const int bt = blockIdx.x;
    const int tid = threadIdx.x;
    __shared__ float h[D_];
    h[tid] = HN[bt * D_ + tid];
    h[tid + 256] = HN[bt * D_ + tid + 256];
    __syncthreads();
    const int warp = tid >> 5, lane = tid & 31;
    for (int o = warp; o < S_ + S_ + DS_; o += 8) {
        const float* wrow;
        if (o < S_) wrow = wg + o * D_;
        else if (o < 2 * S_) wrow = rqw + (o - S_) * D_;
        else wrow = wv + (o - 2 * S_) * D_;
        float s = 0.f;
#pragma unroll
        for (int k = lane; k < D_; k += 32) s += h[k] * wrow[k];
#pragma unroll
        for (int off = 16; off > 0; off >>= 1) s += __shfl_down_sync(0xffffffffu, s, off);
        if (lane == 0) {
            if (o < S_) G[bt * S_ + o] = 1.f / (1.f + expf(-s));
            else if (o < 2 * S_) RQ[bt * S_ + (o - S_)] = s;
            else Vv[bt * DS_ + (o - 2 * S_)] = s;
        }
    }
}

// ---------------- chunked linear-recurrence scan ----------------
__global__ __launch_bounds__(256) void scan_pass1_kernel(
    const float* __restrict__ G, const float* __restrict__ Vv,
    float* __restrict__ CHA, float* __restrict__ CHB)
{
    const int idx = blockIdx.x * 256 + threadIdx.x;
    const int ds = idx % DS_;
    const int s  = (idx / DS_) % S_;
    const int c  = (idx / (DS_ * S_)) % NC_;
    const int b  = idx / (DS_ * S_ * NC_);
    float A = 1.f, Bv = 0.f;
    const int t0 = c * TC_;
    for (int t = t0; t < t0 + TC_; t++) {
        float g = G[(size_t)(b * T_ + t) * S_ + s];
        float a = 1.f - g;
        float bb = g * Vv[(size_t)(b * T_ + t) * DS_ + ds];
        A = a * A;
        Bv = a * Bv + bb;
    }
    CHB[((size_t)(b * S_ + s) * DS_ + ds) * NC_ + c] = Bv;
    if (ds == 0) CHA[(size_t)(b * S_ + s) * NC_ + c] = A;
}

__global__ __launch_bounds__(512) void scan_pass2_kernel(
    const float* __restrict__ CHA, const float* __restrict__ CHB,
    float* __restrict__ MEM, float* __restrict__ CST)
{
    const int idx = threadIdx.x;
    const int ds = idx % DS_;
    const int s  = (idx / DS_) % S_;
    const int b  = idx / (DS_ * S_);
    float st = MEM[idx];
    for (int c = 0; c < NC_; c++) {
        CST[((size_t)(b * S_ + s) * DS_ + ds) * NC_ + c] = st;
        float A = CHA[(size_t)(b * S_ + s) * NC_ + c];
        float Bv = CHB[((size_t)(b * S_ + s) * DS_ + ds) * NC_ + c];
        st = A * st + Bv;
    }
    MEM[idx] = st;
}

__global__ __launch_bounds__(256) void scan_pass3_kernel(
    const float* __restrict__ G, const float* __restrict__ Vv,
    const float* __restrict__ CST, float* __restrict__ MS)
{
    const int idx = blockIdx.x * 256 + threadIdx.x;
    const int ds = idx % DS_;
    const int s  = (idx / DS_) % S_;
    const int c  = (idx / (DS_ * S_)) % NC_;
    const int b  = idx / (DS_ * S_ * NC_);
    float m = CST[((size_t)(b * S_ + s) * DS_ + ds) * NC_ + c];
    const int t0 = c * TC_;
    for (int t = t0; t < t0 + TC_; t++) {
        float g = G[(size_t)(b * T_ + t) * S_ + s];
        float bb = g * Vv[(size_t)(b * T_ + t) * DS_ + ds];
        m = (1.f - g) * m + bb;
        MS[(size_t)(b * T_ + t) * (S_ * DS_) + s * DS_ + ds] = m;
    }
}

// ---------------- softmax read-weights * mem_stack -> split-packed (K=256) ----------------
__global__ __launch_bounds__(128) void rf_split_kernel(
    const float* __restrict__ RQ, const float* __restrict__ MS, unsigned* __restrict__ RF2)
{
    const int bt = blockIdx.x;
    const int t = threadIdx.x;
    __shared__ float q[S_];
    if (t < S_) q[t] = RQ[bt * S_ + t];
    __syncthreads();
    float mx = q[0];
#pragma unroll
    for (int i = 1; i < S_; i++) mx = fmaxf(mx, q[i]);
    float den = 0.f;
#pragma unroll
    for (int i = 0; i < S_; i++) den += expf(q[i] - mx);
    const int k0 = 2 * t;
    const int s = k0 >> 5;
    float wgt = expf(q[s] - mx) / den;
    float y0 = wgt * MS[(size_t)bt * 256 + k0];
    float y1 = wgt * MS[(size_t)bt * 256 + k0 + 1];
    unsigned lo, hi = pack_hilo(y0, y1, lo);
    size_t base = ((size_t)bt * 8 + (t >> 4)) * 32 + (t & 15);
    RF2[base] = hi; RF2[base + 16] = lo;
}

// ---------------- silu(gate)*up -> split-packed (K=2048) ----------------
__global__ __launch_bounds__(256) void silu_split_kernel(
    const float* __restrict__ UPc, unsigned* __restrict__ UP2)
{
    const int idx = blockIdx.x * 256 + threadIdx.x;
    const int bt = idx >> 10;
    const int w = idx & 1023;
    const int f0 = 2 * w;
    float a0 = UPc[(size_t)bt * 4096 + f0];
    float a1 = UPc[(size_t)bt * 4096 + f0 + 1];
    float b0 = UPc[(size_t)bt * 4096 + 2048 + f0];
    float b1 = UPc[(size_t)bt * 4096 + 2048 + f0 + 1];
    float y0 = a0 / (1.f + expf(-a0)) * b0;
    float y1 = a1 / (1.f + expf(-a1)) * b1;
    unsigned lo, hi = pack_hilo(y0, y1, lo);
    size_t base = ((size_t)bt * 64 + (w >> 4)) * 32 + (w & 15);
    UP2[base] = hi; UP2[base + 16] = lo;
}

// ---------------- host orchestration ----------------
static void* devptr(const void* symbol) {
    void* p = nullptr;
    cudaGetSymbolAddress(&p, symbol);
    return p;
}

static inline int cblocks(long long threads) { return (int)((threads + 255) / 256); }

extern "C" void kernel_launch(void* const* d_in, const int* in_sizes, int n_in,
                              void* d_out, int out_size)
{
    const int*   tokens    = (const int*)  d_in[0];
    const float* embed     = (const float*)d_in[1];
    const float* ln_in     = (const float*)d_in[2];
    const float* ln1       = (const float*)d_in[3];
    const float* mixer_up  = (const float*)d_in[4];
    const float* conv_w    = (const float*)d_in[5];
    const float* mixer_down= (const float*)d_in[6];
    const float* ln_mem    = (const float*)d_in[7];
    const float* wg        = (const float*)d_in[8];
    const float* wv        = (const float*)d_in[9];
    const float* rq        = (const float*)d_in[10];
    const float* ro        = (const float*)d_in[11];
    const float* ln2       = (const float*)d_in[12];
    const float* Wgf       = (const float*)d_in[13];
    const float* Wuf       = (const float*)d_in[14];
    const float* Wof       = (const float*)d_in[15];
    const float* ln_out    = (const float*)d_in[16];
    float* out = (float*)d_out;

    float* X   = (float*)devptr(d_X);
    float* HN  = (float*)devptr(d_HN);
    float* GV  = (float*)devptr(d_GV);
    float* G   = (float*)devptr(d_G);
    float* RQ  = (float*)devptr(d_RQ);
    float* Vv  = (float*)devptr(d_V);
    float* MS  = (float*)devptr(d_MS);
    float* UPc = (float*)devptr(d_UPc);
    float* MEM = (float*)devptr(d_MEM);
    float* CHA = (float*)devptr(d_CHA);
    float* CHB = (float*)devptr(d_CHB);
    float* CST = (float*)devptr(d_CST);

    unsigned* HN2 = (unsigned*)devptr(d_HN2);
    unsigned* CG2 = (unsigned*)devptr(d_CG2);
    unsigned* RF2 = (unsigned*)devptr(d_RF2);
    unsigned* UP2 = (unsigned*)devptr(d_UP2);
    unsigned* WMU = (unsigned*)devptr(d_WMU);
    unsigned* WMD = (unsigned*)devptr(d_WMD);
    unsigned* WRO = (unsigned*)devptr(d_WRO);
    unsigned* WFF = (unsigned*)devptr(d_WFF);
    unsigned* WOF = (unsigned*)devptr(d_WOF);
    unsigned* WEM = (unsigned*)devptr(d_WEM);

    cudaFuncSetAttribute(bsgemm_kernel<false>, cudaFuncAttributeMaxDynamicSharedMemorySize, SMEM_B_);
    cudaFuncSetAttribute(bsgemm_kernel<true>,  cudaFuncAttributeMaxDynamicSharedMemorySize, SMEM_B_);

    // launch order: [0] convert WMU, [1] embed_norm(+MEM zero), [2] rmsnorm_split,
    // [3] first bsgemm  <- captured by ncu
    {
        int r = L_ * 2 * D_;
        convert_split_kernel<<<cblocks((long long)r * (D_/2)), 256>>>(mixer_up, WMU, r, D_, r, r, 0);
    }
    embed_norm_kernel<<<BT_, 256>>>(tokens, embed, ln_in, X, MEM);

    const int scanThreads = B_ * S_ * DS_ * NC_;   // 16384

    for (int i = 0; i < L_; i++) {
        const float* ln1_i = ln1 + i * D_;
        const float* cw_i  = conv_w + (size_t)i * D_ * K_;
        const float* lnm_i = ln_mem + i * D_;
        const float* wg_i  = wg + (size_t)i * S_ * D_;
        const float* wv_i  = wv + (size_t)i * DS_ * D_;
        const float* rq_i  = rq + (size_t)i * S_ * D_;
        const float* ln2_i = ln2 + i * D_;

        const unsigned* wmu_i = WMU + (size_t)i * 2 * D_ * D_;
        const unsigned* wmd_i = WMD + (size_t)i * D_ * D_;
        const unsigned* wro_i = WRO + (size_t)i * D_ * S_ * DS_;
        const unsigned* wff_i = WFF + (size_t)i * 2 * FF_ * D_;
        const unsigned* wof_i = WOF + (size_t)i * D_ * FF_;

        // mixer branch
        rmsnorm_split_kernel<<<BT_, 256>>>(X, ln1_i, HN2);
        bsgemm_kernel<false><<<dim3(2 * D_ / 64, BT_ / 128), 256, SMEM_B_>>>(
            HN2, wmu_i, nullptr, GV, BT_, 2 * D_, D_ / 32);

        if (i == 0) {
            int r;
            r = L_ * D_;
            convert_split_kernel<<<cblocks((long long)r * (D_/2)), 256>>>(mixer_down, WMD, r, D_, r, r, 0);
            r = L_ * D_;
            convert_split_kernel<<<cblocks((long long)r * (S_*DS_/2)), 256>>>(ro, WRO, r, S_*DS_, r, r, 0);
            r = L_ * FF_;
            convert_split_kernel<<<cblocks((long long)r * (D_/2)), 256>>>(Wgf, WFF, r, D_, FF_, 2*FF_, 0);
            r = L_ * FF_;
            convert_split_kernel<<<cblocks((long long)r * (D_/2)), 256>>>(Wuf, WFF, r, D_, FF_, 2*FF_, FF_);
            r = L_ * D_;
            convert_split_kernel<<<cblocks((long long)r * (FF_/2)), 256>>>(Wof, WOF, r, FF_, r, r, 0);
            r = V_;
            convert_split_kernel<<<cblocks((long long)r * (D_/2)), 256>>>(embed, WEM, r, D_, r, r, 0);
        }

        conv_gate_split_kernel<<<BT_, 256>>>(GV, cw_i, CG2);
        bsgemm_kernel<true><<<dim3(D_ / 64, BT_ / 128), 256, SMEM_B_>>>(
            CG2, wmd_i, X, X, BT_, D_, D_ / 32);

        // story memory branch
        rmsnorm_kernel<<<BT_, 256>>>(X, lnm_i, HN);
        smallproj_kernel<<<BT_, 256>>>(HN, wg_i, rq_i, wv_i, G, RQ, Vv);
        scan_pass1_kernel<<<scanThreads / 256, 256>>>(G, Vv, CHA, CHB);
        scan_pass2_kernel<<<1, B_ * S_ * DS_>>>(CHA, CHB, MEM, CST);
        scan_pass3_kernel<<<scanThreads / 256, 256>>>(G, Vv, CST, MS);
        rf_split_kernel<<<BT_, 128>>>(RQ, MS, RF2);
        bsgemm_kernel<true><<<dim3(D_ / 64, BT_ / 128), 256, SMEM_B_>>>(
            RF2, wro_i, X, X, BT_, D_, S_ * DS_ / 32);

        // FFN branch (fused gate+up GEMM, N = 4096)
        rmsnorm_split_kernel<<<BT_, 256>>>(X, ln2_i, HN2);
        bsgemm_kernel<false><<<dim3(2 * FF_ / 64, BT_ / 128), 256, SMEM_B_>>>(
            HN2, wff_i, nullptr, UPc, BT_, 2 * FF_, D_ / 32);
        silu_split_kernel<<<cblocks((long long)BT_ * (FF_ / 2)), 256>>>(UPc, UP2);
        bsgemm_kernel<true><<<dim3(D_ / 64, BT_ / 128), 256, SMEM_B_>>>(
            UP2, wof_i, X, X, BT_, D_, FF_ / 32);
    }

    // tied head
    rmsnorm_split_kernel<<<BT_, 256>>>(X, ln_out, HN2);
    bsgemm_kernel<false><<<dim3(V_ / 64, BT_ / 128), 256, SMEM_B_>>>(
        HN2, WEM, nullptr, out, BT_, V_, D_ / 32);
}

// round 9
// speedup vs baseline: 1.2300x; 1.0351x over previous
#include <cuda_runtime.h>
#include <cuda_bf16.h>
#include <stdint.h>
#include <math.h>

// ---------------- problem constants ----------------
#define V_  32000
#define D_  512
#define L_  6
#define FF_ 2048
#define T_  2048
#define B_  2
#define S_  8
#define DS_ 32
#define K_  15

#define BT_ (B_ * T_)          // 4096 tokens
#define NC_ 32                 // scan chunks
#define TC_ (T_ / NC_)         // 64 steps per chunk

// ---------------- device scratch (no allocations allowed) ----------------
__device__ float d_X  [BT_ * D_];
__device__ float d_HN [BT_ * D_];
__device__ float d_GV [BT_ * 2 * D_];
__device__ float d_G  [BT_ * S_];
__device__ float d_RQ [BT_ * S_];
__device__ float d_V  [BT_ * DS_];
__device__ float d_MS [BT_ * S_ * DS_];
__device__ float d_UPc[BT_ * 2 * FF_];
__device__ float d_MEM[B_ * S_ * DS_];
__device__ float d_CHA[B_ * S_ * NC_];
__device__ float d_CHB[B_ * S_ * DS_ * NC_];
__device__ float d_CST[B_ * S_ * DS_ * NC_];

// split-bf16 packed operands, layout per row: [k32 chunk][16 hi words | 16 lo words]
__device__ unsigned d_HN2[BT_ * D_];
__device__ unsigned d_CG2[BT_ * D_];
__device__ unsigned d_RF2[BT_ * S_ * DS_];
__device__ unsigned d_UP2[BT_ * FF_];
__device__ unsigned d_WMU[L_ * 2 * D_ * D_];
__device__ unsigned d_WMD[L_ * D_ * D_];
__device__ unsigned d_WRO[L_ * D_ * S_ * DS_];
__device__ unsigned d_WFF[L_ * 2 * FF_ * D_];
__device__ unsigned d_WOF[L_ * D_ * FF_];
__device__ unsigned d_WEM[V_ * D_];

// ---------------- bf16 split helpers ----------------
__device__ __forceinline__ unsigned pack_hilo(float x0, float x1, unsigned& lo)
{
    __nv_bfloat16 h0 = __float2bfloat16_rn(x0);
    __nv_bfloat16 h1 = __float2bfloat16_rn(x1);
    float l0f = x0 - __bfloat162float(h0);
    float l1f = x1 - __bfloat162float(h1);
    __nv_bfloat16 l0 = __float2bfloat16_rn(l0f);
    __nv_bfloat16 l1 = __float2bfloat16_rn(l1f);
    lo = (unsigned)__bfloat16_as_ushort(l0) | ((unsigned)__bfloat16_as_ushort(l1) << 16);
    return (unsigned)__bfloat16_as_ushort(h0) | ((unsigned)__bfloat16_as_ushort(h1) << 16);
}

__device__ __forceinline__ void mma_bf16(float* c, const unsigned* a, unsigned b0, unsigned b1)
{
    asm volatile(
        "mma.sync.aligned.m16n8k16.row.col.f32.bf16.bf16.f32 "
        "{%0,%1,%2,%3}, {%4,%5,%6,%7}, {%8,%9}, {%0,%1,%2,%3};"
        : "+f"(c[0]), "+f"(c[1]), "+f"(c[2]), "+f"(c[3])
        : "r"(a[0]), "r"(a[1]), "r"(a[2]), "r"(a[3]), "r"(b0), "r"(b1));
}

__device__ __forceinline__ void ldsm4(unsigned& r0, unsigned& r1, unsigned& r2, unsigned& r3,
                                      unsigned saddr)
{
    asm volatile("ldmatrix.sync.aligned.m8n8.x4.shared.b16 {%0,%1,%2,%3}, [%4];"
                 : "=r"(r0), "=r"(r1), "=r"(r2), "=r"(r3) : "r"(saddr));
}

__device__ __forceinline__ void cp16(unsigned saddr, const void* g)
{
    asm volatile("cp.async.cg.shared.global [%0], [%1], 16;" :: "r"(saddr), "l"(g));
}

// ---------------- split-bf16 tensor GEMM: C[M,N] = A @ W^T (+R) ----------------
// 128x64 block tile, 8 warps (4x2), 32x32 warp tile, k-chunk 32, 2-stage cp.async,
// ldmatrix, 3-term split-bf16 (hi*hi + lo*hi + hi*lo) into one accumulator set.
// __launch_bounds__(256,3): <=84 regs -> 3 CTAs/SM (occupancy attack on latency-bound issue).
#define TW_ 20
#define A_W_ (128 * TW_)          // 2560 words per A sub-tile
#define B_W_ (64 * TW_)           // 1280 words per B sub-tile
#define STG_W_ (2 * A_W_ + 2 * B_W_)   // 7680 words per stage
#define SMEM_B_ (2 * STG_W_ * 4)       // 61440 bytes

template<bool RES>
__global__ __launch_bounds__(256, 3)
void bsgemm_kernel(const unsigned* __restrict__ A, const unsigned* __restrict__ W,
                   const float* __restrict__ R, float* __restrict__ C,
                   int M, int N, int KC)   // KC = K/32, KC >= 2
{
    extern __shared__ unsigned sm[];
    const unsigned sbase = (unsigned)__cvta_generic_to_shared(sm);
    const int tid = threadIdx.x, wid = tid >> 5, lane = tid & 31;
    const int grp = lane >> 2, kin = lane & 3;
    const int wm = (wid & 3) * 32, wn = (wid >> 2) * 32;
    const int row0 = blockIdx.y * 128, col0 = blockIdx.x * 64;

    const int ar = tid >> 1, ac = (tid & 1) * 2;
    const int br = tid >> 2, bq = tid & 3;
    const unsigned* Aga = A + ((size_t)(row0 + ar) * KC) * 32 + ac * 4;
    const unsigned* Wgb = W + ((size_t)(col0 + br) * KC) * 32 + bq * 4;
    const unsigned soA = (unsigned)(ar * TW_ + ac * 4) * 4u;
    const unsigned soB = (unsigned)(br * TW_ + bq * 4) * 4u;

    float acc[2][4][4];
#pragma unroll
    for (int i = 0; i < 2; i++)
#pragma unroll
        for (int j = 0; j < 4; j++)
#pragma unroll
            for (int r = 0; r < 4; r++) acc[i][j][r] = 0.f;

#define LOAD_STAGE(c) do {                                                  \
        const unsigned sb = sbase + (unsigned)(((c) & 1) * STG_W_) * 4u;    \
        const unsigned* ap = Aga + (size_t)(c) * 32;                        \
        const unsigned* wp = Wgb + (size_t)(c) * 32;                        \
        cp16(sb + soA,                 ap);                                 \
        cp16(sb + soA + 16,            ap + 4);                             \
        cp16(sb + A_W_ * 4u + soA,      ap + 16);                           \
        cp16(sb + A_W_ * 4u + soA + 16, ap + 20);                           \
        cp16(sb + 2u * A_W_ * 4u + soB,              wp);                   \
        cp16(sb + 2u * A_W_ * 4u + B_W_ * 4u + soB,  wp + 16);              \
        asm volatile("cp.async.commit_group;" ::: "memory");                \
    } while (0)

    LOAD_STAGE(0);

    const int lrow_add = (lane & 7) + ((lane >> 3) & 1) * 8;
    const int lword_add = (lane >> 4) * 4;

    for (int c = 0; c < KC; c++) {
        if (c + 1 < KC) {
            LOAD_STAGE(c + 1);
            asm volatile("cp.async.wait_group 1;" ::: "memory");
        } else {
            asm volatile("cp.async.wait_group 0;" ::: "memory");
        }
        __syncthreads();

        const unsigned sb = sbase + (unsigned)((c & 1) * STG_W_) * 4u;
        const unsigned aHi = sb;
        const unsigned aLo = sb + A_W_ * 4u;
        const unsigned bHi = sb + 2u * A_W_ * 4u;
        const unsigned bLo = bHi + B_W_ * 4u;

#pragma unroll
        for (int s16 = 0; s16 < 2; s16++) {
            const int kw = s16 * 8 + lword_add;
            unsigned ah[2][4], al[2][4], bh[4][2], bl[4][2];
#pragma unroll
            for (int i = 0; i < 2; i++) {
                const unsigned off = (unsigned)((wm + i * 16 + lrow_add) * TW_ + kw) * 4u;
                ldsm4(ah[i][0], ah[i][1], ah[i][2], ah[i][3], aHi + off);
                ldsm4(al[i][0], al[i][1], al[i][2], al[i][3], aLo + off);
            }
#pragma unroll
            for (int jj = 0; jj < 2; jj++) {
                const unsigned off = (unsigned)((wn + jj * 16 + lrow_add) * TW_ + kw) * 4u;
                unsigned q0, q1, q2, q3;
                ldsm4(q0, q1, q2, q3, bHi + off);
                bh[jj * 2][0] = q0; bh[jj * 2 + 1][0] = q1;
                bh[jj * 2][1] = q2; bh[jj * 2 + 1][1] = q3;
                ldsm4(q0, q1, q2, q3, bLo + off);
                bl[jj * 2][0] = q0; bl[jj * 2 + 1][0] = q1;
                bl[jj * 2][1] = q2; bl[jj * 2 + 1][1] = q3;
            }
#pragma unroll
            for (int j = 0; j < 4; j++)
#pragma unroll
                for (int i = 0; i < 2; i++) {
                    mma_bf16(acc[i][j], ah[i], bh[j][0], bh[j][1]);
                    mma_bf16(acc[i][j], al[i], bh[j][0], bh[j][1]);
                    mma_bf16(acc[i][j], ah[i], bl[j][0], bl[j][1]);
                }
        }
        __syncthreads();
    }
#undef LOAD_STAGE

    // epilogue
    const int orow0 = row0 + wm + grp;
    const int ocol0 = col0 + wn + 2 * kin;
#pragma unroll
    for (int i = 0; i < 2; i++) {
#pragma unroll
        for (int j = 0; j < 4; j++) {
            const size_t o0 = (size_t)(orow0 + i * 16) * N + ocol0 + j * 8;
            const size_t o1 = (size_t)(orow0 + i * 16 + 8) * N + ocol0 + j * 8;
            float2 v0 = make_float2(acc[i][j][0], acc[i][j][1]);
            float2 v1 = make_float2(acc[i][j][2], acc[i][j][3]);
            if (RES) {
                float2 r0 = *reinterpret_cast<const float2*>(R + o0);
                float2 r1 = *reinterpret_cast<const float2*>(R + o1);
                v0.x += r0.x; v0.y += r0.y;
                v1.x += r1.x; v1.y += r1.y;
            }
            *reinterpret_cast<float2*>(C + o0) = v0;
            *reinterpret_cast<float2*>(C + o1) = v1;
        }
    }
}

// ---------------- weight converter -> packed split layout (k32 chunks) ----------------
__global__ __launch_bounds__(256) void convert_split_kernel(
    const float* __restrict__ src, unsigned* __restrict__ dst,
    int nRows, int K, int group, int dstride, int dbase)
{
    int kp2 = K >> 1;
    int idx = blockIdx.x * 256 + threadIdx.x;
    if (idx >= nRows * kp2) return;
    int n = idx / kp2, p = idx - n * kp2;
    float x = src[(size_t)n * K + 2 * p];
    float y = src[(size_t)n * K + 2 * p + 1];
    unsigned lo, hi = pack_hilo(x, y, lo);
    int dn = (n / group) * dstride + dbase + (n % group);
    size_t base = ((size_t)dn * (K >> 5) + (p >> 4)) * 32 + (p & 15);
    dst[base] = hi;
    dst[base + 16] = lo;
}

// ---------------- embed gather + rmsnorm(ln_in) -> fp32 X; fused MEM zeroing ----------------
__global__ __launch_bounds__(256) void embed_norm_kernel(
    const int* __restrict__ tokens, const float* __restrict__ embed,
    const float* __restrict__ w, float* __restrict__ out, float* __restrict__ MEM)
{
    const int bt = blockIdx.x;
    const int tid = threadIdx.x;
    if (bt == 0) { MEM[tid] = 0.f; MEM[tid + 256] = 0.f; }
    const int tok = tokens[bt];
    const float* row = embed + (size_t)tok * D_;
    float x0 = row[tid], x1 = row[tid + 256];
    __shared__ float red[256];
    red[tid] = x0 * x0 + x1 * x1;
    __syncthreads();
    for (int s = 128; s > 0; s >>= 1) {
        if (tid < s) red[tid] += red[tid + s];
        __syncthreads();
    }
    float scale = rsqrtf(red[0] / (float)D_ + 1e-6f);
    out[bt * D_ + tid]       = x0 * scale * w[tid];
    out[bt * D_ + tid + 256] = x1 * scale * w[tid + 256];
}

// ---------------- rmsnorm -> fp32 (story-memory branch) ----------------
__global__ __launch_bounds__(256) void rmsnorm_kernel(
    const float* __restrict__ X, const float* __restrict__ w, float* __restrict__ O)
{
    const int bt = blockIdx.x;
    const int tid = threadIdx.x;
    float x0 = X[bt * D_ + tid], x1 = X[bt * D_ + tid + 256];
    __shared__ float red[256];
    red[tid] = x0 * x0 + x1 * x1;
    __syncthreads();
    for (int s = 128; s > 0; s >>= 1) {
        if (tid < s) red[tid] += red[tid + s];
        __syncthreads();
    }
    float scale = rsqrtf(red[0] / (float)D_ + 1e-6f);
    O[bt * D_ + tid]       = x0 * scale * w[tid];
    O[bt * D_ + tid + 256] = x1 * scale * w[tid + 256];
}

// ---------------- rmsnorm -> split-packed (K=512) ----------------
__global__ __launch_bounds__(256) void rmsnorm_split_kernel(
    const float* __restrict__ X, const float* __restrict__ w, unsigned* __restrict__ O)
{
    const int bt = blockIdx.x;
    const int t = threadIdx.x;
    float x0 = X[(size_t)bt * D_ + 2 * t];
    float x1 = X[(size_t)bt * D_ + 2 * t + 1];
    __shared__ float red[256];
    red[t] = x0 * x0 + x1 * x1;
    __syncthreads();
    for (int s = 128; s > 0; s >>= 1) {
        if (t < s) red[t] += red[t + s];
        __syncthreads();
    }
    float sc = rsqrtf(red[0] / (float)D_ + 1e-6f);
    float y0 = x0 * sc * w[2 * t], y1 = x1 * sc * w[2 * t + 1];
    unsigned lo, hi = pack_hilo(y0, y1, lo);
    size_t base = ((size_t)bt * 16 + (t >> 4)) * 32 + (t & 15);
    O[base] = hi; O[base + 16] = lo;
}

// ---------------- causal depthwise conv + gate -> split-packed (K=512) ----------------
__global__ __launch_bounds__(256) void conv_gate_split_kernel(
    const float* __restrict__ GV, const float* __restrict__ cw, unsigned* __restrict__ CG2)
{
    const int idx = blockIdx.x * 256 + threadIdx.x;
    const int w = idx & 255;
    const int bt = idx >> 8;
    const int b = bt / T_, t = bt - b * T_;
    const int d0 = 2 * w;
    float s0 = 0.f, s1 = 0.f;
#pragma unroll
    for (int j = 0; j < K_; j++) {
        int tt = t - (K_ - 1) + j;
        if (tt >= 0) {
            const float* row = GV + (size_t)(b * T_ + tt) * (2 * D_) + D_;
            s0 += row[d0]     * cw[d0 * K_ + j];
            s1 += row[d0 + 1] * cw[(d0 + 1) * K_ + j];
        }
    }
    float g0 = GV[(size_t)bt * (2 * D_) + d0];
    float g1 = GV[(size_t)bt * (2 * D_) + d0 + 1];
    float y0 = s0 / (1.f + expf(-g0));
    float y1 = s1 / (1.f + expf(-g1));
    unsigned lo, hi = pack_hilo(y0, y1, lo);
    size_t base = ((size_t)bt * 16 + (w >> 4)) * 32 + (w & 15);
    CG2[base] = hi; CG2[base + 16] = lo;
}

// ---------------- small projections ----------------
__global__ __launch_bounds__(256) void smallproj_kernel(
    const float* __restrict__ HN, const float* __restrict__ wg,
    const float* __restrict__ rqw, const float* __restrict__ wv,
    float* __restrict__ G, float* __restrict__ RQ, float* __restrict__ Vv)
{
    const int bt = blockIdx.x;
    const int tid = threadIdx.x;
    __shared__ float h[D_];
    h[tid] = HN[bt * D_ + tid];
    h[tid + 256] = HN[bt * D_ + tid + 256];
    __syncthreads();
    const int warp = tid >> 5, lane = tid & 31;
    for (int o = warp; o < S_ + S_ + DS_; o += 8) {
        const float* wrow;
        if (o < S_) wrow = wg + o * D_;
        else if (o < 2 * S_) wrow = rqw + (o - S_) * D_;
        else wrow = wv + (o - 2 * S_) * D_;
        float s = 0.f;
#pragma unroll
        for (int k = lane; k < D_; k += 32) s += h[k] * wrow[k];
#pragma unroll
        for (int off = 16; off > 0; off >>= 1) s += __shfl_down_sync(0xffffffffu, s, off);
        if (lane == 0) {
            if (o < S_) G[bt * S_ + o] = 1.f / (1.f + expf(-s));
            else if (o < 2 * S_) RQ[bt * S_ + (o - S_)] = s;
            else Vv[bt * DS_ + (o - 2 * S_)] = s;
        }
    }
}

// ---------------- chunked linear-recurrence scan ----------------
__global__ __launch_bounds__(256) void scan_pass1_kernel(
    const float* __restrict__ G, const float* __restrict__ Vv,
    float* __restrict__ CHA, float* __restrict__ CHB)
{
    const int idx = blockIdx.x * 256 + threadIdx.x;
    const int ds = idx % DS_;
    const int s  = (idx / DS_) % S_;
    const int c  = (idx / (DS_ * S_)) % NC_;
    const int b  = idx / (DS_ * S_ * NC_);
    float A = 1.f, Bv = 0.f;
    const int t0 = c * TC_;
    for (int t = t0; t < t0 + TC_; t++) {
        float g = G[(size_t)(b * T_ + t) * S_ + s];
        float a = 1.f - g;
        float bb = g * Vv[(size_t)(b * T_ + t) * DS_ + ds];
        A = a * A;
        Bv = a * Bv + bb;
    }
    CHB[((size_t)(b * S_ + s) * DS_ + ds) * NC_ + c] = Bv;
    if (ds == 0) CHA[(size_t)(b * S_ + s) * NC_ + c] = A;
}

__global__ __launch_bounds__(512) void scan_pass2_kernel(
    const float* __restrict__ CHA, const float* __restrict__ CHB,
    float* __restrict__ MEM, float* __restrict__ CST)
{
    const int idx = threadIdx.x;
    const int ds = idx % DS_;
    const int s  = (idx / DS_) % S_;
    const int b  = idx / (DS_ * S_);
    float st = MEM[idx];
    for (int c = 0; c < NC_; c++) {
        CST[((size_t)(b * S_ + s) * DS_ + ds) * NC_ + c] = st;
        float A = CHA[(size_t)(b * S_ + s) * NC_ + c];
        float Bv = CHB[((size_t)(b * S_ + s) * DS_ + ds) * NC_ + c];
        st = A * st + Bv;
    }
    MEM[idx] = st;
}

__global__ __launch_bounds__(256) void scan_pass3_kernel(
    const float* __restrict__ G, const float* __restrict__ Vv,
    const float* __restrict__ CST, float* __restrict__ MS)
{
    const int idx = blockIdx.x * 256 + threadIdx.x;
    const int ds = idx % DS_;
    const int s  = (idx / DS_) % S_;
    const int c  = (idx / (DS_ * S_)) % NC_;
    const int b  = idx / (DS_ * S_ * NC_);
    float m = CST[((size_t)(b * S_ + s) * DS_ + ds) * NC_ + c];
    const int t0 = c * TC_;
    for (int t = t0; t < t0 + TC_; t++) {
        float g = G[(size_t)(b * T_ + t) * S_ + s];
        float bb = g * Vv[(size_t)(b * T_ + t) * DS_ + ds];
        m = (1.f - g) * m + bb;
        MS[(size_t)(b * T_ + t) * (S_ * DS_) + s * DS_ + ds] = m;
    }
}

// ---------------- softmax read-weights * mem_stack -> split-packed (K=256) ----------------
__global__ __launch_bounds__(128) void rf_split_kernel(
    const float* __restrict__ RQ, const float* __restrict__ MS, unsigned* __restrict__ RF2)
{
    const int bt = blockIdx.x;
    const int t = threadIdx.x;
    __shared__ float q[S_];
    if (t < S_) q[t] = RQ[bt * S_ + t];
    __syncthreads();
    float mx = q[0];
#pragma unroll
    for (int i = 1; i < S_; i++) mx = fmaxf(mx, q[i]);
    float den = 0.f;
#pragma unroll
    for (int i = 0; i < S_; i++) den += expf(q[i] - mx);
    const int k0 = 2 * t;
    const int s = k0 >> 5;
    float wgt = expf(q[s] - mx) / den;
    float y0 = wgt * MS[(size_t)bt * 256 + k0];
    float y1 = wgt * MS[(size_t)bt * 256 + k0 + 1];
    unsigned lo, hi = pack_hilo(y0, y1, lo);
    size_t base = ((size_t)bt * 8 + (t >> 4)) * 32 + (t & 15);
    RF2[base] = hi; RF2[base + 16] = lo;
}

// ---------------- silu(gate)*up -> split-packed (K=2048) ----------------
__global__ __launch_bounds__(256) void silu_split_kernel(
    const float* __restrict__ UPc, unsigned* __restrict__ UP2)
{
    const int idx = blockIdx.x * 256 + threadIdx.x;
    const int bt = idx >> 10;
    const int w = idx & 1023;
    const int f0 = 2 * w;
    float a0 = UPc[(size_t)bt * 4096 + f0];
    float a1 = UPc[(size_t)bt * 4096 + f0 + 1];
    float b0 = UPc[(size_t)bt * 4096 + 2048 + f0];
    float b1 = UPc[(size_t)bt * 4096 + 2048 + f0 + 1];
    float y0 = a0 / (1.f + expf(-a0)) * b0;
    float y1 = a1 / (1.f + expf(-a1)) * b1;
    unsigned lo, hi = pack_hilo(y0, y1, lo);
    size_t base = ((size_t)bt * 64 + (w >> 4)) * 32 + (w & 15);
    UP2[base] = hi; UP2[base + 16] = lo;
}

// ---------------- host orchestration ----------------
static void* devptr(const void* symbol) {
    void* p = nullptr;
    cudaGetSymbolAddress(&p, symbol);
    return p;
}

static inline int cblocks(long long threads) { return (int)((threads + 255) / 256); }

extern "C" void kernel_launch(void* const* d_in, const int* in_sizes, int n_in,
                              void* d_out, int out_size)
{
    const int*   tokens    = (const int*)  d_in[0];
    const float* embed     = (const float*)d_in[1];
    const float* ln_in     = (const float*)d_in[2];
    const float* ln1       = (const float*)d_in[3];
    const float* mixer_up  = (const float*)d_in[4];
    const float* conv_w    = (const float*)d_in[5];
    const float* mixer_down= (const float*)d_in[6];
    const float* ln_mem    = (const float*)d_in[7];
    const float* wg        = (const float*)d_in[8];
    const float* wv        = (const float*)d_in[9];
    const float* rq        = (const float*)d_in[10];
    const float* ro        = (const float*)d_in[11];
    const float* ln2       = (const float*)d_in[12];
    const float* Wgf       = (const float*)d_in[13];
    const float* Wuf       = (const float*)d_in[14];
    const float* Wof       = (const float*)d_in[15];
    const float* ln_out    = (const float*)d_in[16];
    float* out = (float*)d_out;

    float* X   = (float*)devptr(d_X);
    float* HN  = (float*)devptr(d_HN);
    float* GV  = (float*)devptr(d_GV);
    float* G   = (float*)devptr(d_G);
    float* RQ  = (float*)devptr(d_RQ);
    float* Vv  = (float*)devptr(d_V);
    float* MS  = (float*)devptr(d_MS);
    float* UPc = (float*)devptr(d_UPc);
    float* MEM = (float*)devptr(d_MEM);
    float* CHA = (float*)devptr(d_CHA);
    float* CHB = (float*)devptr(d_CHB);
    float* CST = (float*)devptr(d_CST);

    unsigned* HN2 = (unsigned*)devptr(d_HN2);
    unsigned* CG2 = (unsigned*)devptr(d_CG2);
    unsigned* RF2 = (unsigned*)devptr(d_RF2);
    unsigned* UP2 = (unsigned*)devptr(d_UP2);
    unsigned* WMU = (unsigned*)devptr(d_WMU);
    unsigned* WMD = (unsigned*)devptr(d_WMD);
    unsigned* WRO = (unsigned*)devptr(d_WRO);
    unsigned* WFF = (unsigned*)devptr(d_WFF);
    unsigned* WOF = (unsigned*)devptr(d_WOF);
    unsigned* WEM = (unsigned*)devptr(d_WEM);

    cudaFuncSetAttribute(bsgemm_kernel<false>, cudaFuncAttributeMaxDynamicSharedMemorySize, SMEM_B_);
    cudaFuncSetAttribute(bsgemm_kernel<true>,  cudaFuncAttributeMaxDynamicSharedMemorySize, SMEM_B_);

    // launch order: [0] convert WMU, [1] embed_norm(+MEM zero), [2] rmsnorm_split,
    // [3] first bsgemm  <- captured by ncu
    {
        int r = L_ * 2 * D_;
        convert_split_kernel<<<cblocks((long long)r * (D_/2)), 256>>>(mixer_up, WMU, r, D_, r, r, 0);
    }
    embed_norm_kernel<<<BT_, 256>>>(tokens, embed, ln_in, X, MEM);

    const int scanThreads = B_ * S_ * DS_ * NC_;   // 16384

    for (int i = 0; i < L_; i++) {
        const float* ln1_i = ln1 + i * D_;
        const float* cw_i  = conv_w + (size_t)i * D_ * K_;
        const float* lnm_i = ln_mem + i * D_;
        const float* wg_i  = wg + (size_t)i * S_ * D_;
        const float* wv_i  = wv + (size_t)i * DS_ * D_;
        const float* rq_i  = rq + (size_t)i * S_ * D_;
        const float* ln2_i = ln2 + i * D_;

        const unsigned* wmu_i = WMU + (size_t)i * 2 * D_ * D_;
        const unsigned* wmd_i = WMD + (size_t)i * D_ * D_;
        const unsigned* wro_i = WRO + (size_t)i * D_ * S_ * DS_;
        const unsigned* wff_i = WFF + (size_t)i * 2 * FF_ * D_;
        const unsigned* wof_i = WOF + (size_t)i * D_ * FF_;

        // mixer branch
        rmsnorm_split_kernel<<<BT_, 256>>>(X, ln1_i, HN2);
        bsgemm_kernel<false><<<dim3(2 * D_ / 64, BT_ / 128), 256, SMEM_B_>>>(
            HN2, wmu_i, nullptr, GV, BT_, 2 * D_, D_ / 32);

        if (i == 0) {
            int r;
            r = L_ * D_;
            convert_split_kernel<<<cblocks((long long)r * (D_/2)), 256>>>(mixer_down, WMD, r, D_, r, r, 0);
            r = L_ * D_;
            convert_split_kernel<<<cblocks((long long)r * (S_*DS_/2)), 256>>>(ro, WRO, r, S_*DS_, r, r, 0);
            r = L_ * FF_;
            convert_split_kernel<<<cblocks((long long)r * (D_/2)), 256>>>(Wgf, WFF, r, D_, FF_, 2*FF_, 0);
            r = L_ * FF_;
            convert_split_kernel<<<cblocks((long long)r * (D_/2)), 256>>>(Wuf, WFF, r, D_, FF_, 2*FF_, FF_);
            r = L_ * D_;
            convert_split_kernel<<<cblocks((long long)r * (FF_/2)), 256>>>(Wof, WOF, r, FF_, r, r, 0);
            r = V_;
            convert_split_kernel<<<cblocks((long long)r * (D_/2)), 256>>>(embed, WEM, r, D_, r, r, 0);
        }

        conv_gate_split_kernel<<<BT_, 256>>>(GV, cw_i, CG2);
        bsgemm_kernel<true><<<dim3(D_ / 64, BT_ / 128), 256, SMEM_B_>>>(
            CG2, wmd_i, X, X, BT_, D_, D_ / 32);

        // story memory branch
        rmsnorm_kernel<<<BT_, 256>>>(X, lnm_i, HN);
        smallproj_kernel<<<BT_, 256>>>(HN, wg_i, rq_i, wv_i, G, RQ, Vv);
        scan_pass1_kernel<<<scanThreads / 256, 256>>>(G, Vv, CHA, CHB);
        scan_pass2_kernel<<<1, B_ * S_ * DS_>>>(CHA, CHB, MEM, CST);
        scan_pass3_kernel<<<scanThreads / 256, 256>>>(G, Vv, CST, MS);
        rf_split_kernel<<<BT_, 128>>>(RQ, MS, RF2);
        bsgemm_kernel<true><<<dim3(D_ / 64, BT_ / 128), 256, SMEM_B_>>>(
            RF2, wro_i, X, X, BT_, D_, S_ * DS_ / 32);

        // FFN branch (fused gate+up GEMM, N = 4096)
        rmsnorm_split_kernel<<<BT_, 256>>>(X, ln2_i, HN2);
        bsgemm_kernel<false><<<dim3(2 * FF_ / 64, BT_ / 128), 256, SMEM_B_>>>(
            HN2, wff_i, nullptr, UPc, BT_, 2 * FF_, D_ / 32);
        silu_split_kernel<<<cblocks((long long)BT_ * (FF_ / 2)), 256>>>(UPc, UP2);
        bsgemm_kernel<true><<<dim3(D_ / 64, BT_ / 128), 256, SMEM_B_>>>(
            UP2, wof_i, X, X, BT_, D_, FF_ / 32);
    }

    // tied head
    rmsnorm_split_kernel<<<BT_, 256>>>(X, ln_out, HN2);
    bsgemm_kernel<false><<<dim3(V_ / 64, BT_ / 128), 256, SMEM_B_>>>(
        HN2, WEM, nullptr, out, BT_, V_, D_ / 32);
}